// round 12
// baseline (speedup 1.0000x reference)
#include <cuda_runtime.h>

// AnalyticalBoundedLineAttractor — analytic piecewise-affine ODE integrator.
//
// Per step: z = Wx + b; m = (z>0); x' = x + p1 + p2 with
//   p1 = DT*(relu(z) - x),  p2 = (m .* (W'p1) - DT*p1)/2,  W' = DT*W.
// K = 2 Taylor terms (measured rel_err 4.6e-4 vs 1e-3 gate).
// Identity: W'p1 = W'relu(z) - DT*(W'x); dot 2 runs on relu(z), the
// -DT*W'x piece folds into off-path algebra (dwx = z - db).
//
// Round-12: TWO INTERLEAVED CHAINS PER WARP-PAIR. Sessions 1-11 established
// the chain is latency-bound with the FMA pipe busy only ~64 of ~200 cyc
// per phase; hiding latency within one chain failed (R10). So each warp
// pair (rows 0-31 / 32-63) now advances TWO batch elements per iteration:
// both chains' LDS/FMA streams live in the same post-barrier basic block
// (ptxas interleaves them), B's work fills A's stall cycles, and ONE
// barrier + ONE set of W registers serve both chains. Per-chain barrier
// cost halves; FMA-pipe per phase (64 FMA2 = 128 cyc) still fits under
// the ~145-cyc latency envelope.
//
// Geometry: block=128 (2 warp-pairs = 4 chains/CTA), grid=64 -> one
// CTA/SM, each warp on its own SMSP. Named 64-thread barrier per pair.
// 99 stored updates (x_100 never needed).

#define DIMV 64
#define DTC  0.05f

using u64 = unsigned long long;

__device__ __forceinline__ u64 fma2(u64 a, u64 b, u64 c) {
    u64 d; asm("fma.rn.f32x2 %0, %1, %2, %3;" : "=l"(d) : "l"(a), "l"(b), "l"(c));
    return d;
}
__device__ __forceinline__ u64 add2(u64 a, u64 b) {
    u64 d; asm("add.rn.f32x2 %0, %1, %2;" : "=l"(d) : "l"(a), "l"(b));
    return d;
}
__device__ __forceinline__ u64 pack2(float lo, float hi) {
    u64 d; asm("mov.b64 %0, {%1, %2};" : "=l"(d) : "f"(lo), "f"(hi));
    return d;
}

__global__ void __launch_bounds__(128, 1)
attractor_kernel(const float* __restrict__ x0,
                 const float* __restrict__ Wg,
                 const float* __restrict__ bg,
                 float* __restrict__ out,
                 int tsteps)
{
    __shared__ __align__(16) float xs[2][2][DIMV];   // [pair][chain][i] x buf
    __shared__ __align__(16) float rs[2][2][DIMV];   // [pair][chain][i] relu buf

    const int tid  = threadIdx.x;
    const int pr   = tid >> 6;                     // warp-pair 0/1
    const int i    = tid & 63;                     // row index
    const int elemA = blockIdx.x * 4 + pr * 2;     // two chains per pair
    const int elemB = elemA + 1;
    const int bar  = pr + 1;                       // named barrier per pair

    // ---- W row i, pre-scaled by DT, as 32 packed f32x2 pairs (shared by
    // both chains) ----
    u64 w2[32];
    {
        const float* wrow = Wg + i * DIMV;
#pragma unroll
        for (int q = 0; q < 16; q++) {
            float4 t = reinterpret_cast<const float4*>(wrow)[q];
            float s0 = t.x * DTC, s1 = t.y * DTC, s2 = t.z * DTC, s3 = t.w * DTC;
            asm("mov.b64 %0, {%1, %2};" : "=l"(w2[2*q])   : "f"(s0), "f"(s1));
            asm("mov.b64 %0, {%1, %2};" : "=l"(w2[2*q+1]) : "f"(s2), "f"(s3));
        }
    }
    const float db  = DTC * bg[i];                 // DT * b_i
    const u64 dbin  = pack2(db, 0.f);              // dot-1 accumulator seed

    float xiA = x0[(size_t)elemA * DIMV + i];
    float xiB = x0[(size_t)elemB * DIMV + i];
    xs[pr][0][i] = xiA;
    xs[pr][1][i] = xiB;
    float* outA = out + (size_t)elemA * tsteps * DIMV + i;
    float* outB = out + (size_t)elemB * tsteps * DIMV + i;
    *outA = xiA;                                   // x_0 stored up front
    *outB = xiB;
    asm volatile("bar.sync %0, 64;" :: "r"(bar) : "memory");

    // dual dot: both chains' 16 LDS.128 + 32 fma.f32x2 streams interleaved
    // in one block so B's FMAs fill A's scoreboard stalls. 4 accs per chain.
    auto dot2x = [&](const float* bufA, const float* bufB,
                     u64 seedA, u64 seedB, float& rA, float& rB) {
        const ulonglong2* pA = reinterpret_cast<const ulonglong2*>(bufA);
        const ulonglong2* pB = reinterpret_cast<const ulonglong2*>(bufB);
        u64 aA0 = seedA, aA1 = 0ull, aA2 = 0ull, aA3 = 0ull;
        u64 aB0 = seedB, aB1 = 0ull, aB2 = 0ull, aB3 = 0ull;
#pragma unroll
        for (int q = 0; q < 16; q += 2) {
            ulonglong2 vA0 = pA[q];
            ulonglong2 vB0 = pB[q];
            ulonglong2 vA1 = pA[q + 1];
            ulonglong2 vB1 = pB[q + 1];
            aA0 = fma2(w2[2*q + 0], vA0.x, aA0);
            aB0 = fma2(w2[2*q + 0], vB0.x, aB0);
            aA1 = fma2(w2[2*q + 1], vA0.y, aA1);
            aB1 = fma2(w2[2*q + 1], vB0.y, aB1);
            aA2 = fma2(w2[2*q + 2], vA1.x, aA2);
            aB2 = fma2(w2[2*q + 2], vB1.x, aB2);
            aA3 = fma2(w2[2*q + 3], vA1.y, aA3);
            aB3 = fma2(w2[2*q + 3], vB1.y, aB3);
        }
        u64 sA = add2(add2(aA0, aA1), add2(aA2, aA3));
        u64 sB = add2(add2(aB0, aB1), add2(aB2, aB3));
        float lA, hA, lB, hB;
        asm("mov.b64 {%0, %1}, %2;" : "=f"(lA), "=f"(hA) : "l"(sA));
        asm("mov.b64 {%0, %1}, %2;" : "=f"(lB), "=f"(hB) : "l"(sB));
        rA = lA + hA;
        rB = lB + hB;
    };

    // 99 updates: x_100 is never stored, so never computed.
#pragma unroll 1
    for (int t = 1; t < tsteps; t++) {
        const float c1A = (1.0f - DTC) * xiA;      // hides in dot-1 window
        const float dxA = DTC * xiA;
        const float c1B = (1.0f - DTC) * xiB;
        const float dxB = DTC * xiB;

        // phase 1: z = (W'x)_i + DT*b_i for both chains
        float zA, zB;
        dot2x(xs[pr][0], xs[pr][1], dbin, dbin, zA, zB);
        float reluA = fmaxf(zA, 0.f);
        float reluB = fmaxf(zB, 0.f);
        rs[pr][0][i] = reluA;
        rs[pr][1][i] = reluB;
        asm volatile("bar.sync %0, 64;" :: "r"(bar) : "memory");

        // off critical path (overlaps barrier + phase-2 LDS/FMA streams):
        bool  mA = zA > 0.f,  mB = zB > 0.f;
        float p1A = reluA - dxA,  p1B = reluB - dxB;
        float dwA = zA - db,      dwB = zB - db;
        float inA = fmaf(-0.5f * DTC, p1A, reluA + c1A)
                  - (mA ? 0.5f * DTC * dwA : 0.f);
        float inB = fmaf(-0.5f * DTC, p1B, reluB + c1B)
                  - (mB ? 0.5f * DTC * dwB : 0.f);

        // phase 2: t2 = (W' relu)_i ; x' = inner + 0.5*(m ? t2 : 0)
        float t2A, t2B;
        dot2x(rs[pr][0], rs[pr][1], 0ull, 0ull, t2A, t2B);
        xiA = fmaf(mA ? t2A : 0.f, 0.5f, inA);
        xiB = fmaf(mB ? t2B : 0.f, 0.5f, inB);

        xs[pr][0][i] = xiA;                        // readers retired at bar above
        xs[pr][1][i] = xiB;
        outA += DIMV; *outA = xiA;                 // off-chain trajectory stores
        outB += DIMV; *outB = xiB;
        asm volatile("bar.sync %0, 64;" :: "r"(bar) : "memory");
    }
}

extern "C" void kernel_launch(void* const* d_in, const int* in_sizes, int n_in,
                              void* d_out, int out_size)
{
    const float* x0 = (const float*)d_in[0];   // (batch, 64)
    const float* W  = (const float*)d_in[1];   // (64, 64)
    const float* b  = (const float*)d_in[2];   // (64,)
    float* out = (float*)d_out;                // (batch, T, 64)

    int batch  = in_sizes[0] / DIMV;           // 256
    int tsteps = out_size / (batch * DIMV);    // 100

    attractor_kernel<<<batch / 4, 128>>>(x0, W, b, out, tsteps);
}

// round 13
// speedup vs baseline: 1.3069x; 1.3069x over previous
#include <cuda_runtime.h>

// AnalyticalBoundedLineAttractor — analytic piecewise-affine ODE integrator.
//
// Per step: z = Wx + b; m = (z>0); x' = x + p1 + p2 with
//   p1 = DT*(relu(z) - x),  p2 = (m .* (W'p1) - DT*p1)/2,  W' = DT*W.
// K = 2 Taylor terms (measured rel_err 4.6e-4 vs 1e-3 gate).
// Identity: W'p1 = W'relu(z) - DT*(W'x); dot 2 runs on relu(z), the
// -DT*W'x piece folds into off-path algebra (dwx = z - db).
//
// Round-13: WARP-PRIVATE ELEMENT. One warp = one element; lane j owns
// rows j and j+32. Exchange remains smem broadcast (16 LDS.128 serve both
// rows), but producer == consumer warp, so the 47-cyc cross-warp named
// barrier becomes a ~23-cyc __syncwarp and all cross-warp skew vanishes.
// Single buffer is hazard-free: a warp's phase-1 LDS instructions all
// issue in program order before its phase-2 STS (in-order smem pipe);
// __syncwarp gives visibility + compiler fence. FMA2/lane doubles to 64
// per phase (rt-2 -> 128 issue-cyc spine) but replaces barrier dead time.
// Loads batched into register arrays BEFORE the FMA blocks (R12 lesson:
// force MLP explicitly, don't trust ptxas).
//
// Geometry: block=128 (4 warps = 4 elements), grid=64 -> one CTA/SM,
// warps on 4 distinct SMSPs, all 256 chains concurrent in one wave.
// 99 stored updates (x_100 never needed).

#define DIMV 64
#define DTC  0.05f

using u64 = unsigned long long;

__device__ __forceinline__ u64 fma2(u64 a, u64 b, u64 c) {
    u64 d; asm("fma.rn.f32x2 %0, %1, %2, %3;" : "=l"(d) : "l"(a), "l"(b), "l"(c));
    return d;
}
__device__ __forceinline__ u64 add2(u64 a, u64 b) {
    u64 d; asm("add.rn.f32x2 %0, %1, %2;" : "=l"(d) : "l"(a), "l"(b));
    return d;
}
__device__ __forceinline__ u64 pack2(float lo, float hi) {
    u64 d; asm("mov.b64 %0, {%1, %2};" : "=l"(d) : "f"(lo), "f"(hi));
    return d;
}

__global__ void __launch_bounds__(128, 1)
attractor_kernel(const float* __restrict__ x0,
                 const float* __restrict__ Wg,
                 const float* __restrict__ bg,
                 float* __restrict__ out,
                 int tsteps)
{
    __shared__ __align__(16) float bufs[4][DIMV];  // one vector buffer per warp

    const int lane = threadIdx.x & 31;
    const int w    = threadIdx.x >> 5;             // warp = element within CTA
    const int elem = blockIdx.x * 4 + w;
    const int r0   = lane;                         // owned rows
    const int r1   = lane + 32;
    float* buf = bufs[w];

    // ---- W rows r0 and r1, pre-scaled by DT, as packed f32x2 pairs ----
    u64 wa[32], wb[32];
    {
        const float* wr0 = Wg + r0 * DIMV;
        const float* wr1 = Wg + r1 * DIMV;
#pragma unroll
        for (int q = 0; q < 16; q++) {
            float4 ta = reinterpret_cast<const float4*>(wr0)[q];
            float4 tb = reinterpret_cast<const float4*>(wr1)[q];
            wa[2*q]   = pack2(ta.x * DTC, ta.y * DTC);
            wa[2*q+1] = pack2(ta.z * DTC, ta.w * DTC);
            wb[2*q]   = pack2(tb.x * DTC, tb.y * DTC);
            wb[2*q+1] = pack2(tb.z * DTC, tb.w * DTC);
        }
    }
    const float db0 = DTC * bg[r0];
    const float db1 = DTC * bg[r1];
    const u64 seed0 = pack2(db0, 0.f);
    const u64 seed1 = pack2(db1, 0.f);

    float xi0 = x0[(size_t)elem * DIMV + r0];
    float xi1 = x0[(size_t)elem * DIMV + r1];
    float* outp = out + (size_t)elem * tsteps * DIMV;
    outp[r0] = xi0;                                // x_0 stored up front
    outp[r1] = xi1;

    // dual-row dot over the warp-private buffer: 16 LDS.128 (batched into
    // registers first -> full MLP) + 64 fma.f32x2 (4 accs per row, reuse
    // distance 8 cyc > lat 4).
    auto dot2 = [&](u64 sA, u64 sB, float& yA, float& yB) {
        const ulonglong2* p16 = reinterpret_cast<const ulonglong2*>(buf);
        ulonglong2 v[16];
#pragma unroll
        for (int q = 0; q < 16; q++) v[q] = p16[q];     // all loads in flight
        u64 aA0 = sA, aA1 = 0ull, aA2 = 0ull, aA3 = 0ull;
        u64 aB0 = sB, aB1 = 0ull, aB2 = 0ull, aB3 = 0ull;
#pragma unroll
        for (int q = 0; q < 16; q += 2) {
            aA0 = fma2(wa[2*q + 0], v[q].x,     aA0);
            aB0 = fma2(wb[2*q + 0], v[q].x,     aB0);
            aA1 = fma2(wa[2*q + 1], v[q].y,     aA1);
            aB1 = fma2(wb[2*q + 1], v[q].y,     aB1);
            aA2 = fma2(wa[2*q + 2], v[q + 1].x, aA2);
            aB2 = fma2(wb[2*q + 2], v[q + 1].x, aB2);
            aA3 = fma2(wa[2*q + 3], v[q + 1].y, aA3);
            aB3 = fma2(wb[2*q + 3], v[q + 1].y, aB3);
        }
        u64 sAo = add2(add2(aA0, aA1), add2(aA2, aA3));
        u64 sBo = add2(add2(aB0, aB1), add2(aB2, aB3));
        float lA, hA, lB, hB;
        asm("mov.b64 {%0, %1}, %2;" : "=f"(lA), "=f"(hA) : "l"(sAo));
        asm("mov.b64 {%0, %1}, %2;" : "=f"(lB), "=f"(hB) : "l"(sBo));
        yA = lA + hA;
        yB = lB + hB;
    };

    // 99 updates: x_100 is never stored, so never computed.
#pragma unroll 1
    for (int t = 1; t < tsteps; t++) {
        const float c10 = (1.0f - DTC) * xi0;      // hides in phase-1 window
        const float dx0 = DTC * xi0;
        const float c11 = (1.0f - DTC) * xi1;
        const float dx1 = DTC * xi1;

        // phase 1: exchange x, z = (W'x)_r + DT*b_r out of the tree
        buf[r0] = xi0;
        buf[r1] = xi1;
        __syncwarp();
        float z0, z1;
        dot2(seed0, seed1, z0, z1);
        float relu0 = fmaxf(z0, 0.f);
        float relu1 = fmaxf(z1, 0.f);

        // phase 2: exchange relu(z) (in-order smem pipe: phase-1 loads
        // already issued; __syncwarp fences visibility)
        buf[r0] = relu0;
        buf[r1] = relu1;
        __syncwarp();

        // off critical path (overlaps phase-2 LDS/FMA stream):
        bool  m0 = z0 > 0.f,      m1 = z1 > 0.f;
        float p10 = relu0 - dx0,  p11 = relu1 - dx1;
        float dw0 = z0 - db0,     dw1 = z1 - db1;
        float in0 = fmaf(-0.5f * DTC, p10, relu0 + c10)
                  - (m0 ? 0.5f * DTC * dw0 : 0.f);
        float in1 = fmaf(-0.5f * DTC, p11, relu1 + c11)
                  - (m1 ? 0.5f * DTC * dw1 : 0.f);

        float t20, t21;
        dot2(0ull, 0ull, t20, t21);
        xi0 = fmaf(m0 ? t20 : 0.f, 0.5f, in0);     // sel + fma only
        xi1 = fmaf(m1 ? t21 : 0.f, 0.5f, in1);

        outp += DIMV;                              // off-chain trajectory store
        outp[r0] = xi0;
        outp[r1] = xi1;
    }
}

extern "C" void kernel_launch(void* const* d_in, const int* in_sizes, int n_in,
                              void* d_out, int out_size)
{
    const float* x0 = (const float*)d_in[0];   // (batch, 64)
    const float* W  = (const float*)d_in[1];   // (64, 64)
    const float* b  = (const float*)d_in[2];   // (64,)
    float* out = (float*)d_out;                // (batch, T, 64)

    int batch  = in_sizes[0] / DIMV;           // 256
    int tsteps = out_size / (batch * DIMV);    // 100

    attractor_kernel<<<batch / 4, 128>>>(x0, W, b, out, tsteps);
}

// round 14
// speedup vs baseline: 1.6139x; 1.2349x over previous
#include <cuda_runtime.h>

// AnalyticalBoundedLineAttractor — analytic piecewise-affine ODE integrator.
//
// Per step: z = Wx + b; m = (z>0); x' = x + p1 + p2 with
//   p1 = DT*(relu(z) - x),  p2 = (m .* (W'p1) - DT*p1)/2,  W' = DT*W.
// K = 2 Taylor terms (measured rel_err 4.6e-4 vs 1e-3 gate).
// Identity: W'p1 = W'relu(z) - DT*(W'x); dot 2 runs on relu(z), the
// -DT*W'x piece folds into off-path algebra (dwx = z - db).
//
// Architecture = measured optimum (R11): 2 elements per 128-thread CTA,
// grid=128 (one CTA/SM, 4 warps on 4 SMSPs), dot = 16 LDS.128 +
// 32 fma.rn.f32x2, 4 packed accumulators, DT*b seeded into the dot-1
// accumulator, relu exchanged (not p1), sel+fma tails, 99 stored updates.
//
// Round-14: SPLIT-BARRIER producer/consumer exchange. Each symmetric
// bar.sync becomes an asymmetric pair (warp0: arrive A / sync B;
// warp1: arrive B / sync A — CUTLASS named-barrier handoff). All
// off-path work (trajectory STG, pointer inc, mask/inner algebra,
// next-step FMULs) moves BETWEEN arrive and sync, executing while the
// partner is still arriving instead of on the post-release chain.
// 4 barriers per element (phase1 A/B, phase2 C/D): a warp cannot
// re-arrive at A before passing sync D, which needs the partner past
// sync A -> no double-arm race. Barrier ids 1..8.

#define DIMV 64
#define DTC  0.05f

using u64 = unsigned long long;

__device__ __forceinline__ u64 fma2(u64 a, u64 b, u64 c) {
    u64 d; asm("fma.rn.f32x2 %0, %1, %2, %3;" : "=l"(d) : "l"(a), "l"(b), "l"(c));
    return d;
}
__device__ __forceinline__ u64 add2(u64 a, u64 b) {
    u64 d; asm("add.rn.f32x2 %0, %1, %2;" : "=l"(d) : "l"(a), "l"(b));
    return d;
}
__device__ __forceinline__ u64 pack2(float lo, float hi) {
    u64 d; asm("mov.b64 %0, {%1, %2};" : "=l"(d) : "f"(lo), "f"(hi));
    return d;
}
#define BAR_ARRIVE(id) asm volatile("bar.arrive %0, 64;" :: "r"(id) : "memory")
#define BAR_SYNC(id)   asm volatile("bar.sync %0, 64;"   :: "r"(id) : "memory")

__global__ void __launch_bounds__(128, 1)
attractor_kernel(const float* __restrict__ x0,
                 const float* __restrict__ Wg,
                 const float* __restrict__ bg,
                 float* __restrict__ out,
                 int tsteps)
{
    __shared__ __align__(16) float xs[2][DIMV];    // x exchange buffer
    __shared__ __align__(16) float rs[2][DIMV];    // relu(z) exchange buffer

    const int tid  = threadIdx.x;
    const int el   = tid >> 6;                     // local element 0/1
    const int i    = tid & 63;                     // row index
    const int w01  = (tid >> 5) & 1;               // warp within element
    const int elem = blockIdx.x * 2 + el;

    // split-barrier ids: phase1 pair {A,B}, phase2 pair {C,D} per element
    const int b1a = 1 + el * 4 + w01;              // I arrive (phase 1)
    const int b1s = 1 + el * 4 + (1 - w01);        // I sync   (phase 1)
    const int b2a = 3 + el * 4 + w01;              // I arrive (phase 2)
    const int b2s = 3 + el * 4 + (1 - w01);        // I sync   (phase 2)

    // ---- W row i, pre-scaled by DT, as 32 packed f32x2 pairs ----
    u64 w2[32];
    {
        const float* wrow = Wg + i * DIMV;
#pragma unroll
        for (int q = 0; q < 16; q++) {
            float4 t = reinterpret_cast<const float4*>(wrow)[q];
            w2[2*q]   = pack2(t.x * DTC, t.y * DTC);
            w2[2*q+1] = pack2(t.z * DTC, t.w * DTC);
        }
    }
    const float db  = DTC * bg[i];                 // DT * b_i
    const u64 dbin  = pack2(db, 0.f);              // dot-1 accumulator seed
    float xi = x0[(size_t)elem * DIMV + i];

    xs[el][i] = xi;
    float* outp = out + (size_t)elem * tsteps * DIMV + i;
    *outp = xi;                                    // x_0 stored up front
    BAR_ARRIVE(b2a);                               // prime step loop via phase-2 pair
    float c1xi = (1.0f - DTC) * xi;
    float dxi  = DTC * xi;
    BAR_SYNC(b2s);

    // dot(DT*W_row_i, buf) + seed: 16 x LDS.128 + 32 x fma.f32x2, 4 accs
    auto dot = [&](const float* buf, u64 seed) -> float {
        const ulonglong2* p16 = reinterpret_cast<const ulonglong2*>(buf);
        u64 a0 = seed, a1 = 0ull, a2 = 0ull, a3 = 0ull;
#pragma unroll
        for (int q = 0; q < 16; q += 2) {
            ulonglong2 v0 = p16[q];
            ulonglong2 v1 = p16[q + 1];
            a0 = fma2(w2[2*q + 0], v0.x, a0);
            a1 = fma2(w2[2*q + 1], v0.y, a1);
            a2 = fma2(w2[2*q + 2], v1.x, a2);
            a3 = fma2(w2[2*q + 3], v1.y, a3);
        }
        u64 s = add2(add2(a0, a1), add2(a2, a3));
        float lo, hi;
        asm("mov.b64 {%0, %1}, %2;" : "=f"(lo), "=f"(hi) : "l"(s));
        return lo + hi;
    };

    // 99 updates: x_100 is never stored, so never computed.
#pragma unroll 1
    for (int t = 1; t < tsteps; t++) {
        // phase 1: z = (W'x)_i + DT*b_i straight out of the tree
        float z    = dot(xs[el], dbin);
        float relu = fmaxf(z, 0.f);                // FMNMX, lat 4
        rs[el][i]  = relu;
        BAR_ARRIVE(b1a);                           // my half of rs published

        // inside the wait window (partner still arriving):
        bool  m      = z > 0.f;
        float p1     = relu - dxi;
        float dwx    = z - db;
        float inner  = fmaf(-0.5f * DTC, p1, relu + c1xi);
        float inner2 = inner - (m ? 0.5f * DTC * dwx : 0.f);

        BAR_SYNC(b1s);                             // partner's half visible

        // phase 2: t2 = (W' relu)_i ; x' = inner2 + 0.5 * (m ? t2 : 0)
        float t2 = dot(rs[el], 0ull);
        xi = fmaf(m ? t2 : 0.f, 0.5f, inner2);     // sel + fma only
        xs[el][i] = xi;                            // xs readers retired at b1
        BAR_ARRIVE(b2a);                           // my half of xs published

        // inside the wait window:
        outp += DIMV;
        *outp = xi;                                // off-chain trajectory store
        c1xi = (1.0f - DTC) * xi;
        dxi  = DTC * xi;

        BAR_SYNC(b2s);                             // partner's half visible
    }
}

extern "C" void kernel_launch(void* const* d_in, const int* in_sizes, int n_in,
                              void* d_out, int out_size)
{
    const float* x0 = (const float*)d_in[0];   // (batch, 64)
    const float* W  = (const float*)d_in[1];   // (64, 64)
    const float* b  = (const float*)d_in[2];   // (64,)
    float* out = (float*)d_out;                // (batch, T, 64)

    int batch  = in_sizes[0] / DIMV;           // 256
    int tsteps = out_size / (batch * DIMV);    // 100

    attractor_kernel<<<batch / 2, 128>>>(x0, W, b, out, tsteps);
}